// round 3
// baseline (speedup 1.0000x reference)
#include <cuda_runtime.h>
#include <stdint.h>

#define FULL 0xffffffffu

constexpr int Bb = 8;
constexpr int Nn = 16384;
constexpr int Gg = 257;
constexpr int Kk = 32;

// Sphere-grid centers (filled by init kernel each launch; deterministic).
__device__ float g_cx[Gg];
__device__ float g_cy[Gg];
__device__ float g_cz[Gg];

// Build the 0.25-spaced lattice inside the unit ball, in meshgrid('ij') order.
__global__ void init_centers_kernel() {
    __shared__ int pf[736];
    int t = threadIdx.x;            // 736 threads
    int keep = 0;
    float x = 0.f, y = 0.f, z = 0.f;
    if (t < 729) {
        int i = t / 81, j = (t / 9) % 9, k = t % 9;
        x = 0.25f * (float)i - 1.0f;   // exact multiples of 0.25
        y = 0.25f * (float)j - 1.0f;
        z = 0.25f * (float)k - 1.0f;
        float n2 = x * x + y * y + z * z;   // exact (multiples of 0.0625)
        keep = (n2 <= 1.00001f) ? 1 : 0;    // matches norm <= 1 + 1e-6
    }
    pf[t] = keep;
    __syncthreads();
    for (int s = 1; s < 736; s <<= 1) {
        int v = (t >= s) ? pf[t - s] : 0;
        __syncthreads();
        pf[t] += v;
        __syncthreads();
    }
    if (keep) {
        int p = pf[t] - 1;    // exclusive position
        g_cx[p] = x; g_cy[p] = y; g_cz[p] = z;
    }
}

// One warp per center; full point cloud staged in SMEM.
// Top-32 kept sorted ascending across lanes as 64-bit keys:
//   key = order_preserving_bits(d2) << 32 | point_index
// reproducing jax.lax.top_k(-d2) ordering incl. tie-break by lower index.
__global__ __launch_bounds__(512, 1)
void knn_group_kernel(const float* __restrict__ xyz,
                      const float* __restrict__ labels,
                      const float* __restrict__ inside,
                      float* __restrict__ out) {
    extern __shared__ float s[];            // 16384 * 3 floats = 192 KB
    const int b = blockIdx.y;

    // Cooperative cloud load (float4-vectorized, perfectly coalesced).
    {
        const float4* src = reinterpret_cast<const float4*>(xyz + (size_t)b * Nn * 3);
        float4* dst = reinterpret_cast<float4*>(s);
        const int nv = Nn * 3 / 4;          // 12288
        for (int i = threadIdx.x; i < nv; i += blockDim.x) dst[i] = src[i];
    }
    __syncthreads();

    const int wid  = threadIdx.x >> 5;
    const int lane = threadIdx.x & 31;
    const int g = blockIdx.x * 16 + wid;
    if (g >= Gg) return;

    const float cx = g_cx[g], cy = g_cy[g], cz = g_cz[g];
    const float c2 = cx * cx + cy * cy + cz * cz;   // exact for lattice coords

    unsigned long long key    = ~0ull;   // lane r holds rank-r key (ascending)
    unsigned long long thresh = ~0ull;   // current 32nd-best (lane 31's key)

    #pragma unroll 4
    for (int it = 0; it < Nn / 32; ++it) {
        const int p = it * 32 + lane;
        const float x = s[3 * p + 0];
        const float y = s[3 * p + 1];
        const float z = s[3 * p + 2];

        // Reference rounding model (H3): fp-contraction everywhere.
        //   x2 : fma chain  fma(z,z, fma(y,y, rn(x*x)))   (XLA fused reduce)
        //   cx : fma chain  fma(cz,z, fma(cy,y, rn(cx*x)))  (cuBLAS K=3 dot)
        //   d2 = (c2 + x2) - 2*cx   (2*cx exact)
        const float x2 = __fmaf_rn(z, z, __fmaf_rn(y, y, __fmul_rn(x, x)));
        const float dt = __fmaf_rn(cz, z, __fmaf_rn(cy, y, __fmul_rn(cx, x)));
        const float d2 = __fsub_rn(__fadd_rn(c2, x2), __fmul_rn(2.0f, dt));

        unsigned u = __float_as_uint(d2);
        u = (u & 0x80000000u) ? ~u : (u | 0x80000000u);   // order-preserving
        const unsigned long long nk =
            ((unsigned long long)u << 32) | (unsigned)p;

        unsigned m = __ballot_sync(FULL, nk < thresh);
        while (m) {
            const int srcl = __ffs(m) - 1;
            m &= m - 1;
            const unsigned long long cand = __shfl_sync(FULL, nk, srcl);
            if (cand >= thresh) continue;   // thresh tightened since ballot
            const int pos = __popc(__ballot_sync(FULL, key < cand));
            const unsigned long long up = __shfl_up_sync(FULL, key, 1);
            if (lane > pos)       key = up;     // shift ranks pos..30 up; drop old 31
            else if (lane == pos) key = cand;   // insert
            thresh = __shfl_sync(FULL, key, 31);
        }
    }

    // Emit outputs: lane r handles rank r. Gather point from SMEM.
    const int idx = (int)(key & 0xffffffffu);
    const float px = s[3 * idx + 0];
    const float py = s[3 * idx + 1];
    const float pz = s[3 * idx + 2];
    const int bg = b * Gg + g;

    // Output layout (tuple flattened, all fp32):
    //   [0] neighborhood [B,G,32,3]  [1] center [B,G,3]
    //   [2] labels_g [B,G,32,1]      [3] idx_groups [B,G,32]
    //   [4] inside_g [B,G,32,1]
    float* o0 = out;
    float* o1 = o0 + (size_t)Bb * Gg * Kk * 3;
    float* o2 = o1 + (size_t)Bb * Gg * 3;
    float* o3 = o2 + (size_t)Bb * Gg * Kk;
    float* o4 = o3 + (size_t)Bb * Gg * Kk;

    const int r0 = (bg * Kk + lane) * 3;
    o0[r0 + 0] = __fsub_rn(px, cx);
    o0[r0 + 1] = __fsub_rn(py, cy);
    o0[r0 + 2] = __fsub_rn(pz, cz);
    if (lane == 0) {
        o1[bg * 3 + 0] = cx;
        o1[bg * 3 + 1] = cy;
        o1[bg * 3 + 2] = cz;
    }
    o2[bg * Kk + lane] = labels[b * Nn + idx];
    o3[bg * Kk + lane] = (float)idx;
    o4[bg * Kk + lane] = inside[b * Nn + idx];
}

extern "C" void kernel_launch(void* const* d_in, const int* in_sizes, int n_in,
                              void* d_out, int out_size) {
    const float* xyz    = (const float*)d_in[0];
    const float* labels = (const float*)d_in[1];
    const float* inside = (const float*)d_in[2];
    float* out = (float*)d_out;

    (void)in_sizes; (void)n_in; (void)out_size;

    init_centers_kernel<<<1, 736>>>();

    const int smem = Nn * 3 * sizeof(float);   // 196608 B
    cudaFuncSetAttribute(knn_group_kernel,
                         cudaFuncAttributeMaxDynamicSharedMemorySize, smem);
    dim3 grid((Gg + 15) / 16, Bb);
    knn_group_kernel<<<grid, 512, smem>>>(xyz, labels, inside, out);
}

// round 4
// speedup vs baseline: 1.0492x; 1.0492x over previous
#include <cuda_runtime.h>
#include <stdint.h>

#define FULL 0xffffffffu

constexpr int Bb = 8;
constexpr int Nn = 16384;
constexpr int Gg = 257;
constexpr int Kk = 32;
constexpr int UU = 8;                 // points per lane per ballot round
constexpr int ROUNDS = Nn / (32 * UU); // 64

// Sphere-grid centers (filled by init kernel each launch; deterministic).
__device__ float g_cx[Gg];
__device__ float g_cy[Gg];
__device__ float g_cz[Gg];

// Build the 0.25-spaced lattice inside the unit ball, in meshgrid('ij') order.
__global__ void init_centers_kernel() {
    __shared__ int pf[736];
    int t = threadIdx.x;            // 736 threads
    int keep = 0;
    float x = 0.f, y = 0.f, z = 0.f;
    if (t < 729) {
        int i = t / 81, j = (t / 9) % 9, k = t % 9;
        x = 0.25f * (float)i - 1.0f;   // exact multiples of 0.25
        y = 0.25f * (float)j - 1.0f;
        z = 0.25f * (float)k - 1.0f;
        float n2 = x * x + y * y + z * z;   // exact (multiples of 0.0625)
        keep = (n2 <= 1.00001f) ? 1 : 0;    // matches norm <= 1 + 1e-6
    }
    pf[t] = keep;
    __syncthreads();
    for (int s = 1; s < 736; s <<= 1) {
        int v = (t >= s) ? pf[t - s] : 0;
        __syncthreads();
        pf[t] += v;
        __syncthreads();
    }
    if (keep) {
        int p = pf[t] - 1;    // exclusive position
        g_cx[p] = x; g_cy[p] = y; g_cz[p] = z;
    }
}

// One warp per center; full point cloud staged in SMEM.
// Top-32 kept sorted ascending across lanes as 64-bit keys:
//   key = order_preserving_bits(d2) << 32 | point_index
// reproducing jax.lax.top_k(-d2) ordering incl. tie-break by lower index.
__global__ __launch_bounds__(512, 1)
void knn_group_kernel(const float* __restrict__ xyz,
                      const float* __restrict__ labels,
                      const float* __restrict__ inside,
                      float* __restrict__ out) {
    extern __shared__ float s[];            // 16384 * 3 floats = 192 KB
    const int b = blockIdx.y;

    // Cooperative cloud load (float4-vectorized, perfectly coalesced).
    {
        const float4* src = reinterpret_cast<const float4*>(xyz + (size_t)b * Nn * 3);
        float4* dst = reinterpret_cast<float4*>(s);
        const int nv = Nn * 3 / 4;          // 12288
        for (int i = threadIdx.x; i < nv; i += blockDim.x) dst[i] = src[i];
    }
    __syncthreads();

    const int wid  = threadIdx.x >> 5;
    const int lane = threadIdx.x & 31;
    const int g = blockIdx.x * 16 + wid;
    if (g >= Gg) return;

    const float cx = g_cx[g], cy = g_cy[g], cz = g_cz[g];
    const float c2 = cx * cx + cy * cy + cz * cz;   // exact for lattice coords

    unsigned long long key    = ~0ull;   // lane r holds rank-r key (ascending)
    unsigned long long thresh = ~0ull;   // current 32nd-best (lane 31's key)
    float thresh_f = __int_as_float(0x7f800000);  // +inf: everything is a hit

    for (int it = 0; it < ROUNDS; ++it) {
        const int base = it * (32 * UU) + lane;

        // 8 independent distance chains: ILP hides LDS + FMA latency.
        float d2v[UU];
        float xv[UU], yv[UU], zv[UU];
        #pragma unroll
        for (int u = 0; u < UU; ++u) {
            const int p = base + 32 * u;
            xv[u] = s[3 * p + 0];
            yv[u] = s[3 * p + 1];
            zv[u] = s[3 * p + 2];
        }
        #pragma unroll
        for (int u = 0; u < UU; ++u) {
            // FROZEN precision model (verified rel_err == 0):
            //   x2 : fma(z,z, fma(y,y, rn(x*x)))
            //   dt : fma(cz,z, fma(cy,y, rn(cx*x)))
            //   d2 = (c2 + x2) - 2*dt
            const float x2 = __fmaf_rn(zv[u], zv[u],
                             __fmaf_rn(yv[u], yv[u], __fmul_rn(xv[u], xv[u])));
            const float dt = __fmaf_rn(cz, zv[u],
                             __fmaf_rn(cy, yv[u], __fmul_rn(cx, xv[u])));
            d2v[u] = __fsub_rn(__fadd_rn(c2, x2), __fmul_rn(2.0f, dt));
        }

        // Conservative float-domain filter (ties pass; recheck exact below).
        bool hit = false;
        #pragma unroll
        for (int u = 0; u < UU; ++u) hit |= !(d2v[u] > thresh_f);

        if (__ballot_sync(FULL, hit)) {
            // Slow path: exact 64-bit key insertion, one ballot per u.
            #pragma unroll
            for (int u = 0; u < UU; ++u) {
                unsigned uu = __float_as_uint(d2v[u]);
                uu = (uu & 0x80000000u) ? ~uu : (uu | 0x80000000u);
                const unsigned long long nk =
                    ((unsigned long long)uu << 32) | (unsigned)(base + 32 * u);

                unsigned m = __ballot_sync(FULL, nk < thresh);
                while (m) {
                    const int srcl = __ffs(m) - 1;
                    m &= m - 1;
                    const unsigned long long cand = __shfl_sync(FULL, nk, srcl);
                    if (cand >= thresh) continue;   // thresh tightened since
                    const int pos = __popc(__ballot_sync(FULL, key < cand));
                    const unsigned long long up = __shfl_up_sync(FULL, key, 1);
                    if (lane > pos)       key = up;     // shift, drop old 31
                    else if (lane == pos) key = cand;   // insert
                    thresh = __shfl_sync(FULL, key, 31);
                }
            }
            // Refresh float threshold from the exact 32nd-best key.
            const unsigned tu = (unsigned)(thresh >> 32);
            const unsigned ob = (tu & 0x80000000u) ? (tu ^ 0x80000000u) : ~tu;
            thresh_f = __uint_as_float(ob);   // NaN while unfilled -> all hit
        }
    }

    // Emit outputs: lane r handles rank r. Gather point from SMEM.
    const int idx = (int)(key & 0xffffffffu);
    const float px = s[3 * idx + 0];
    const float py = s[3 * idx + 1];
    const float pz = s[3 * idx + 2];
    const int bg = b * Gg + g;

    // Output layout (tuple flattened, all fp32):
    //   [0] neighborhood [B,G,32,3]  [1] center [B,G,3]
    //   [2] labels_g [B,G,32,1]      [3] idx_groups [B,G,32]
    //   [4] inside_g [B,G,32,1]
    float* o0 = out;
    float* o1 = o0 + (size_t)Bb * Gg * Kk * 3;
    float* o2 = o1 + (size_t)Bb * Gg * 3;
    float* o3 = o2 + (size_t)Bb * Gg * Kk;
    float* o4 = o3 + (size_t)Bb * Gg * Kk;

    const int r0 = (bg * Kk + lane) * 3;
    o0[r0 + 0] = __fsub_rn(px, cx);
    o0[r0 + 1] = __fsub_rn(py, cy);
    o0[r0 + 2] = __fsub_rn(pz, cz);
    if (lane == 0) {
        o1[bg * 3 + 0] = cx;
        o1[bg * 3 + 1] = cy;
        o1[bg * 3 + 2] = cz;
    }
    o2[bg * Kk + lane] = labels[b * Nn + idx];
    o3[bg * Kk + lane] = (float)idx;
    o4[bg * Kk + lane] = inside[b * Nn + idx];
}

extern "C" void kernel_launch(void* const* d_in, const int* in_sizes, int n_in,
                              void* d_out, int out_size) {
    const float* xyz    = (const float*)d_in[0];
    const float* labels = (const float*)d_in[1];
    const float* inside = (const float*)d_in[2];
    float* out = (float*)d_out;

    (void)in_sizes; (void)n_in; (void)out_size;

    init_centers_kernel<<<1, 736>>>();

    const int smem = Nn * 3 * sizeof(float);   // 196608 B
    cudaFuncSetAttribute(knn_group_kernel,
                         cudaFuncAttributeMaxDynamicSharedMemorySize, smem);
    dim3 grid((Gg + 15) / 16, Bb);
    knn_group_kernel<<<grid, 512, smem>>>(xyz, labels, inside, out);
}